// round 12
// baseline (speedup 1.0000x reference)
#include <cuda_runtime.h>
#include <cuda_fp16.h>

// Problem constants
#define NU   100000
#define NI   50000
#define NN   150000            // NU + NI
#define DD   64
#define NNZV 3200000           // symmetrized nnz
#define NNZH 1600000           // one direction (input edge count)
#define BB   4096
#define SCAN_BS 1024
#define NB1  ((NN + SCAN_BS - 1) / SCAN_BS)   // 147 tiles
#define NBIN 256

// Scratch (device globals; zero-initialized at load; g_cnt/g_tile_desc/g_bin/
// g_binoff re-zeroed by k_score each call for replay determinism).
// s-buffers have NN+1 rows: row NN is a permanent all-zero dummy pad row.
__device__ __half g_s0[(NN + 1) * DD];    // s_l = inv_sqrt ⊙ x_l, fp16
__device__ __half g_s1[(NN + 1) * DD];
__device__ __half g_s2[(NN + 1) * DD];
__device__ __half g_s3[(NN + 1) * DD];
__device__ int    g_col[NNZV];      // CSR column indices (values not needed)
__device__ int    g_cnt[NN];        // histogram -> scatter cursors
__device__ int    g_rowptr[NN + 1];
__device__ int    g_perm[NN];       // rows sorted by degree
__device__ int    g_bin[NBIN];      // degree-bin histogram
__device__ int    g_binoff[NBIN];   // per-bin running offset (counting sort)
__device__ unsigned long long g_tile_desc[NB1];

// ---------------------------------------------------------------------------
// Launch 0: degree histogram (symmetry: read half the edges, count both ends)
// ---------------------------------------------------------------------------
__global__ void k_hist(const int4* __restrict__ rows4, const int4* __restrict__ cols4) {
    int stride = gridDim.x * blockDim.x;
    for (int e = blockIdx.x * blockDim.x + threadIdx.x; e < NNZH / 4; e += stride) {
        int4 u = __ldg(&rows4[e]);
        int4 v = __ldg(&cols4[e]);
        atomicAdd(&g_cnt[u.x], 1); atomicAdd(&g_cnt[v.x], 1);
        atomicAdd(&g_cnt[u.y], 1); atomicAdd(&g_cnt[v.y], 1);
        atomicAdd(&g_cnt[u.z], 1); atomicAdd(&g_cnt[v.z], 1);
        atomicAdd(&g_cnt[u.w], 1); atomicAdd(&g_cnt[v.w], 1);
    }
}

// ---------------------------------------------------------------------------
// Launch 1: exclusive scan (decoupled lookback) + block-aggregated degree-bin
// histogram (for the counting sort)
// ---------------------------------------------------------------------------
__global__ void k_scan() {
    __shared__ int sh[SCAN_BS];
    __shared__ int sbin[NBIN];
    __shared__ int sh_excl;
    int t = threadIdx.x;
    int b = blockIdx.x;
    int i = b * SCAN_BS + t;
    int v = (i < NN) ? g_cnt[i] : 0;

    if (t < NBIN) sbin[t] = 0;
    sh[t] = v;
    __syncthreads();
    if (i < NN) atomicAdd(&sbin[min(v, NBIN - 1)], 1);   // smem pre-aggregation
#pragma unroll
    for (int off = 1; off < SCAN_BS; off <<= 1) {
        int y = (t >= off) ? sh[t - off] : 0;
        __syncthreads();
        sh[t] += y;
        __syncthreads();
    }
    int incl = sh[t];
    int total = sh[SCAN_BS - 1];

    if (b == 0) {
        if (t == 0) {
            *(volatile unsigned long long*)&g_tile_desc[0] = (2ull << 32) | (unsigned)total;
            sh_excl = 0;
        }
    } else {
        if (t == 0)
            *(volatile unsigned long long*)&g_tile_desc[b] = (1ull << 32) | (unsigned)total;
        if (t < 32) {
            int excl = 0;
            int j = b - 1 - t;
            while (true) {
                int st, val;
                do {
                    if (j >= 0) {
                        unsigned long long d = *(volatile unsigned long long*)&g_tile_desc[j];
                        st  = (int)(d >> 32);
                        val = (int)(d & 0xffffffffu);
                    } else { st = 2; val = 0; }
                } while (__any_sync(0xffffffffu, st == 0));
                unsigned pm = __ballot_sync(0xffffffffu, st == 2);
                if (pm) {
                    int p = __ffs(pm) - 1;
                    int contrib = (t <= p) ? val : 0;
                    excl += __reduce_add_sync(0xffffffffu, contrib);
                    break;
                }
                excl += __reduce_add_sync(0xffffffffu, val);
                j -= 32;
            }
            if (t == 0) {
                sh_excl = excl;
                *(volatile unsigned long long*)&g_tile_desc[b] =
                    (2ull << 32) | (unsigned)(excl + total);
            }
        }
    }
    __syncthreads();
    int base = sh_excl;
    if (i < NN) {
        int ex = base + incl - v;
        g_rowptr[i] = ex;
        g_cnt[i]    = ex;            // scatter cursor
    }
    if (b == NB1 - 1 && t == 0) g_rowptr[NN] = NNZV;
    if (t < NBIN && sbin[t]) atomicAdd(&g_bin[t], sbin[t]);   // flush bins
}

// ---------------------------------------------------------------------------
// Launch 2: fused prep (s0 fp16, shfl-shared isq), symmetric edge scatter,
// and block-aggregated counting-sort perm (binscan-free: each block scans
// g_bin in smem for the global prefix; per-bin running offsets via g_binoff).
// ---------------------------------------------------------------------------
__global__ void k_prep_scatter(const float4* __restrict__ ue4, const float4* __restrict__ ie4,
                               const int4* __restrict__ rows4, const int4* __restrict__ cols4) {
    __shared__ int sprefix[NBIN];
    __shared__ int sbin_cnt[NBIN];
    __shared__ int sbase[NBIN];

    int stride = gridDim.x * blockDim.x;
    int t   = threadIdx.x;
    int tid = blockIdx.x * blockDim.x + t;

    // ---- perm phase (block b covers rows [b*256, b*256+255]) ----
    {
        // block-local exclusive scan of the global bin histogram
        int bv = g_bin[t];
        sprefix[t] = bv;
        sbin_cnt[t] = 0;
        __syncthreads();
#pragma unroll
        for (int off = 1; off < NBIN; off <<= 1) {
            int y = (t >= off) ? sprefix[t - off] : 0;
            __syncthreads();
            sprefix[t] += y;
            __syncthreads();
        }
        // sprefix[t] is inclusive; exclusive = sprefix[t] - bv
        int r = blockIdx.x * 256 + t;
        int bin = 0, myrank = 0;
        bool valid = r < NN;
        if (valid) {
            int deg = g_rowptr[r + 1] - g_rowptr[r];
            bin = min(deg, NBIN - 1);
            myrank = atomicAdd(&sbin_cnt[bin], 1);
        }
        __syncthreads();
        if (sbin_cnt[t] > 0)
            sbase[t] = (sprefix[t] - bv) + atomicAdd(&g_binoff[t], sbin_cnt[t]);
        __syncthreads();
        if (valid)
            g_perm[sbase[bin] + myrank] = r;
    }

    // ---- s0 conversion: 16 threads per row share isq via shfl ----
    uint2* s0 = (uint2*)g_s0;
    const int HALF = NU * 16;
    for (int i = tid; i < NN * 16; i += stride) {
        int r = i >> 4;
        float isq = 0.f;
        if ((t & 15) == 0) {            // one lane per 16-group computes
            int deg = g_rowptr[r + 1] - g_rowptr[r];
            isq = rsqrtf(fmaxf((float)deg, 1.f));
        }
        isq = __shfl_sync(0xffffffffu, isq, t & 16);   // lane 0 or 16 of warp
        float4 v = (i < HALF) ? ue4[i] : ie4[i - HALF];
        half2 h0 = __floats2half2_rn(v.x * isq, v.y * isq);
        half2 h1 = __floats2half2_rn(v.z * isq, v.w * isq);
        uint2 o;
        o.x = *(unsigned*)&h0;
        o.y = *(unsigned*)&h1;
        s0[i] = o;
    }

    // ---- symmetric edge scatter ----
    for (int e = tid; e < NNZH / 4; e += stride) {
        int4 uu = __ldg(&rows4[e]);
        int4 cc = __ldg(&cols4[e]);
        int p;
        p = atomicAdd(&g_cnt[uu.x], 1); g_col[p] = cc.x;
        p = atomicAdd(&g_cnt[cc.x], 1); g_col[p] = uu.x;
        p = atomicAdd(&g_cnt[uu.y], 1); g_col[p] = cc.y;
        p = atomicAdd(&g_cnt[cc.y], 1); g_col[p] = uu.y;
        p = atomicAdd(&g_cnt[uu.z], 1); g_col[p] = cc.z;
        p = atomicAdd(&g_cnt[cc.z], 1); g_col[p] = uu.z;
        p = atomicAdd(&g_cnt[uu.w], 1); g_col[p] = cc.w;
        p = atomicAdd(&g_cnt[cc.w], 1); g_col[p] = uu.w;
    }
}

// ---------------------------------------------------------------------------
// Launches 3-5: SpMM over degree-sorted rows: t[r] = sum s[c]; s_next = t/deg.
// FOUR rows/warp (near-equal degrees), 8 lanes/row, uint4 = 8 halves/lane.
// Double-buffered 8-edge smem staging: stage chunk k+8 while gathering chunk
// k -> staging-LDG latency fully hidden; one syncwarp per chunk.
// ---------------------------------------------------------------------------
template <int L>
__global__ void __launch_bounds__(256) k_spmm() {
    const uint4* __restrict__ src4 =
        (const uint4*)(L == 0 ? g_s0 : L == 1 ? g_s1 : g_s2);
    uint4* __restrict__ dst4 =
        (uint4*)(L == 0 ? g_s1 : L == 1 ? g_s2 : g_s3);

    __shared__ int smc[8][2][4][9];   // [warp][buf][row-in-warp][8 + pad]
    int lane = threadIdx.x & 31;
    int w    = threadIdx.x >> 5;
    int q    = lane >> 3;
    int sub  = lane & 7;

    int ri = blockIdx.x * 32 + (w << 2) + q;    // position in sorted order
    bool valid = ri < NN;
    int r = 0, s = 0, deg = 0;
    if (valid) {
        r   = g_perm[ri];
        s   = g_rowptr[r];
        deg = g_rowptr[r + 1] - s;
    }
    int trip = deg;
    trip = max(trip, __shfl_xor_sync(0xffffffffu, trip, 8));
    trip = max(trip, __shfl_xor_sync(0xffffffffu, trip, 16));

    half2 a0 = __float2half2_rn(0.f), a1 = a0, a2 = a0, a3 = a0;

    // preload chunk 0
    smc[w][0][q][sub] = (sub < deg) ? __ldg(&g_col[s + sub]) : NN;
    int buf = 0;
    for (int k = 0; k < trip; k += 8) {
        __syncwarp();
        int nb = buf ^ 1;
        if (k + 8 < trip) {              // stage next chunk into other buffer
            int idx = k + 8 + sub;
            smc[w][nb][q][sub] = (idx < deg) ? __ldg(&g_col[s + idx]) : NN;
        }
#pragma unroll
        for (int j = 0; j < 8; ++j) {
            int cj = smc[w][buf][q][j];     // broadcast within row-group
            uint4 v = src4[cj * 8 + sub];   // LDG.128: 8 halves (row NN = 0)
            a0 = __hadd2(a0, *(half2*)&v.x);
            a1 = __hadd2(a1, *(half2*)&v.y);
            a2 = __hadd2(a2, *(half2*)&v.z);
            a3 = __hadd2(a3, *(half2*)&v.w);
        }
        buf = nb;
    }

    if (valid) {
        float isq2 = 1.f / fmaxf((float)deg, 1.f);   // isq^2 == 1/deg
        float2 f0 = __half22float2(a0), f1 = __half22float2(a1);
        float2 f2 = __half22float2(a2), f3 = __half22float2(a3);
        half2 h0 = __floats2half2_rn(f0.x * isq2, f0.y * isq2);
        half2 h1 = __floats2half2_rn(f1.x * isq2, f1.y * isq2);
        half2 h2 = __floats2half2_rn(f2.x * isq2, f2.y * isq2);
        half2 h3 = __floats2half2_rn(f3.x * isq2, f3.y * isq2);
        uint4 o;
        o.x = *(unsigned*)&h0; o.y = *(unsigned*)&h1;
        o.z = *(unsigned*)&h2; o.w = *(unsigned*)&h3;
        dst4[r * 8 + sub] = o;              // STG.128 (128B per row)
    }
}

// ---------------------------------------------------------------------------
// Launch 6: scorer + replay-state reset
// ---------------------------------------------------------------------------
__global__ void k_score(const int* __restrict__ uids, const int* __restrict__ iids,
                        const float2* __restrict__ ue2, const float2* __restrict__ ie2,
                        float* __restrict__ out) {
    int gtid = blockIdx.x * blockDim.x + threadIdx.x;
    int w = gtid >> 5;
    int lane = threadIdx.x & 31;
    if (w < BB) {
        const half2* s1 = (const half2*)g_s1;
        const half2* s2 = (const half2*)g_s2;
        const half2* s3 = (const half2*)g_s3;

        int u  = uids[w];
        int ri = NU + iids[w];

        int du = g_rowptr[u + 1] - g_rowptr[u];
        float sdu = sqrtf(fmaxf((float)du, 1.f));
        int ou = u * 32 + lane;
        float2 x0u = ue2[ou];
        float2 a = __half22float2(s1[ou]);
        float2 b = __half22float2(s2[ou]);
        float2 c = __half22float2(s3[ou]);
        float eux = x0u.x + sdu * (a.x + b.x + c.x);
        float euy = x0u.y + sdu * (a.y + b.y + c.y);

        int di = g_rowptr[ri + 1] - g_rowptr[ri];
        float sdi = sqrtf(fmaxf((float)di, 1.f));
        int oi = ri * 32 + lane;
        float2 x0i = ie2[oi - NU * 32];
        float2 d = __half22float2(s1[oi]);
        float2 f = __half22float2(s2[oi]);
        float2 g = __half22float2(s3[oi]);
        float eix = x0i.x + sdi * (d.x + f.x + g.x);
        float eiy = x0i.y + sdi * (d.y + f.y + g.y);

        float sres = eux * eix + euy * eiy;
#pragma unroll
        for (int o = 16; o; o >>= 1) sres += __shfl_xor_sync(0xffffffffu, sres, o);
        if (lane == 0) out[w] = sres * 0.0625f;   // 1/(L+1)^2
    }
    // reset replay state
    int stride = gridDim.x * blockDim.x;
    for (int i = gtid; i < NN; i += stride) g_cnt[i] = 0;
    for (int i = gtid; i < NB1; i += stride) g_tile_desc[i] = 0ull;
    for (int i = gtid; i < NBIN; i += stride) { g_bin[i] = 0; g_binoff[i] = 0; }
}

// ---------------------------------------------------------------------------
extern "C" void kernel_launch(void* const* d_in, const int* in_sizes, int n_in,
                              void* d_out, int out_size) {
    const float* ue   = (const float*)d_in[0];
    const float* ie   = (const float*)d_in[1];
    // d_in[2] (adj_vals) unused: vals == isq[r]*isq[c], rebuilt from degrees
    const int*   rows = (const int*)  d_in[3];
    const int*   cols = (const int*)  d_in[4];
    const int*   uids = (const int*)  d_in[5];
    const int*   iids = (const int*)  d_in[6];
    float*       out  = (float*)d_out;

    k_hist        <<< 2048, 256 >>>((const int4*)rows, (const int4*)cols);  // 0
    k_scan        <<< NB1, SCAN_BS >>>();                                   // 1
    k_prep_scatter<<< 2048, 256 >>>((const float4*)ue, (const float4*)ie,
                                    (const int4*)rows, (const int4*)cols);  // 2

    const int spmm_blocks = (NN + 31) / 32;                   // 4688
    k_spmm<0><<< spmm_blocks, 256 >>>();                      // 3 <- ncu capture
    k_spmm<1><<< spmm_blocks, 256 >>>();                      // 4
    k_spmm<2><<< spmm_blocks, 256 >>>();                      // 5

    k_score<<< 512, 256 >>>(uids, iids, (const float2*)ue, (const float2*)ie, out);  // 6
}

// round 13
// speedup vs baseline: 1.0793x; 1.0793x over previous
#include <cuda_runtime.h>
#include <cuda_fp16.h>

// Problem constants
#define NU   100000
#define NI   50000
#define NN   150000            // NU + NI
#define DD   64
#define NNZV 3200000           // symmetrized nnz
#define NNZH 1600000           // one direction (input edge count)
#define BB   4096
#define SCAN_BS 1024
#define NB1  ((NN + SCAN_BS - 1) / SCAN_BS)   // 147 tiles
#define NBIN 256

// Scratch (device globals; zero-initialized at load; g_cnt/g_tile_desc/g_bin/
// g_binoff re-zeroed by k_score each call for replay determinism).
// s-buffers have NN+1 rows: row NN is a permanent all-zero dummy pad row
// (stays L1-resident -> pad gathers cost no L2 bandwidth).
__device__ __half g_s0[(NN + 1) * DD];    // s_l = inv_sqrt ⊙ x_l, fp16
__device__ __half g_s1[(NN + 1) * DD];
__device__ __half g_s2[(NN + 1) * DD];
__device__ __half g_s3[(NN + 1) * DD];
__device__ int    g_col[NNZV];      // CSR column indices (values not needed)
__device__ int    g_cnt[NN];        // histogram -> scatter cursors
__device__ int    g_rowptr[NN + 1];
__device__ int    g_perm[NN];       // rows sorted by degree
__device__ int    g_bin[NBIN];      // degree-bin histogram
__device__ int    g_binoff[NBIN];   // per-bin running offset (counting sort)
__device__ unsigned long long g_tile_desc[NB1];

// ---------------------------------------------------------------------------
// Launch 0: degree histogram (symmetry: read half the edges, count both ends)
// ---------------------------------------------------------------------------
__global__ void k_hist(const int4* __restrict__ rows4, const int4* __restrict__ cols4) {
    int stride = gridDim.x * blockDim.x;
    for (int e = blockIdx.x * blockDim.x + threadIdx.x; e < NNZH / 4; e += stride) {
        int4 u = __ldg(&rows4[e]);
        int4 v = __ldg(&cols4[e]);
        atomicAdd(&g_cnt[u.x], 1); atomicAdd(&g_cnt[v.x], 1);
        atomicAdd(&g_cnt[u.y], 1); atomicAdd(&g_cnt[v.y], 1);
        atomicAdd(&g_cnt[u.z], 1); atomicAdd(&g_cnt[v.z], 1);
        atomicAdd(&g_cnt[u.w], 1); atomicAdd(&g_cnt[v.w], 1);
    }
}

// ---------------------------------------------------------------------------
// Launch 1: exclusive scan (decoupled lookback) + block-aggregated degree-bin
// histogram (for the counting sort)
// ---------------------------------------------------------------------------
__global__ void k_scan() {
    __shared__ int sh[SCAN_BS];
    __shared__ int sbin[NBIN];
    __shared__ int sh_excl;
    int t = threadIdx.x;
    int b = blockIdx.x;
    int i = b * SCAN_BS + t;
    int v = (i < NN) ? g_cnt[i] : 0;

    if (t < NBIN) sbin[t] = 0;
    sh[t] = v;
    __syncthreads();
    if (i < NN) atomicAdd(&sbin[min(v, NBIN - 1)], 1);   // smem pre-aggregation
#pragma unroll
    for (int off = 1; off < SCAN_BS; off <<= 1) {
        int y = (t >= off) ? sh[t - off] : 0;
        __syncthreads();
        sh[t] += y;
        __syncthreads();
    }
    int incl = sh[t];
    int total = sh[SCAN_BS - 1];

    if (b == 0) {
        if (t == 0) {
            *(volatile unsigned long long*)&g_tile_desc[0] = (2ull << 32) | (unsigned)total;
            sh_excl = 0;
        }
    } else {
        if (t == 0)
            *(volatile unsigned long long*)&g_tile_desc[b] = (1ull << 32) | (unsigned)total;
        if (t < 32) {
            int excl = 0;
            int j = b - 1 - t;
            while (true) {
                int st, val;
                do {
                    if (j >= 0) {
                        unsigned long long d = *(volatile unsigned long long*)&g_tile_desc[j];
                        st  = (int)(d >> 32);
                        val = (int)(d & 0xffffffffu);
                    } else { st = 2; val = 0; }
                } while (__any_sync(0xffffffffu, st == 0));
                unsigned pm = __ballot_sync(0xffffffffu, st == 2);
                if (pm) {
                    int p = __ffs(pm) - 1;
                    int contrib = (t <= p) ? val : 0;
                    excl += __reduce_add_sync(0xffffffffu, contrib);
                    break;
                }
                excl += __reduce_add_sync(0xffffffffu, val);
                j -= 32;
            }
            if (t == 0) {
                sh_excl = excl;
                *(volatile unsigned long long*)&g_tile_desc[b] =
                    (2ull << 32) | (unsigned)(excl + total);
            }
        }
    }
    __syncthreads();
    int base = sh_excl;
    if (i < NN) {
        int ex = base + incl - v;
        g_rowptr[i] = ex;
        g_cnt[i]    = ex;            // scatter cursor
    }
    if (b == NB1 - 1 && t == 0) g_rowptr[NN] = NNZV;
    if (t < NBIN && sbin[t]) atomicAdd(&g_bin[t], sbin[t]);   // flush bins
}

// ---------------------------------------------------------------------------
// Launch 2: fused prep (s0 fp16, shfl-shared isq), symmetric edge scatter,
// and block-aggregated counting-sort perm
// ---------------------------------------------------------------------------
__global__ void k_prep_scatter(const float4* __restrict__ ue4, const float4* __restrict__ ie4,
                               const int4* __restrict__ rows4, const int4* __restrict__ cols4) {
    __shared__ int sprefix[NBIN];
    __shared__ int sbin_cnt[NBIN];
    __shared__ int sbase[NBIN];

    int stride = gridDim.x * blockDim.x;
    int t   = threadIdx.x;
    int tid = blockIdx.x * blockDim.x + t;

    // ---- perm phase (block b covers rows [b*256, b*256+255]) ----
    {
        int bv = g_bin[t];
        sprefix[t] = bv;
        sbin_cnt[t] = 0;
        __syncthreads();
#pragma unroll
        for (int off = 1; off < NBIN; off <<= 1) {
            int y = (t >= off) ? sprefix[t - off] : 0;
            __syncthreads();
            sprefix[t] += y;
            __syncthreads();
        }
        int r = blockIdx.x * 256 + t;
        int bin = 0, myrank = 0;
        bool valid = r < NN;
        if (valid) {
            int deg = g_rowptr[r + 1] - g_rowptr[r];
            bin = min(deg, NBIN - 1);
            myrank = atomicAdd(&sbin_cnt[bin], 1);
        }
        __syncthreads();
        if (sbin_cnt[t] > 0)
            sbase[t] = (sprefix[t] - bv) + atomicAdd(&g_binoff[t], sbin_cnt[t]);
        __syncthreads();
        if (valid)
            g_perm[sbase[bin] + myrank] = r;
    }

    // ---- s0 conversion: 16 threads per row share isq via shfl ----
    uint2* s0 = (uint2*)g_s0;
    const int HALF = NU * 16;
    for (int i = tid; i < NN * 16; i += stride) {
        int r = i >> 4;
        float isq = 0.f;
        if ((t & 15) == 0) {
            int deg = g_rowptr[r + 1] - g_rowptr[r];
            isq = rsqrtf(fmaxf((float)deg, 1.f));
        }
        isq = __shfl_sync(0xffffffffu, isq, t & 16);
        float4 v = (i < HALF) ? ue4[i] : ie4[i - HALF];
        half2 h0 = __floats2half2_rn(v.x * isq, v.y * isq);
        half2 h1 = __floats2half2_rn(v.z * isq, v.w * isq);
        uint2 o;
        o.x = *(unsigned*)&h0;
        o.y = *(unsigned*)&h1;
        s0[i] = o;
    }

    // ---- symmetric edge scatter ----
    for (int e = tid; e < NNZH / 4; e += stride) {
        int4 uu = __ldg(&rows4[e]);
        int4 cc = __ldg(&cols4[e]);
        int p;
        p = atomicAdd(&g_cnt[uu.x], 1); g_col[p] = cc.x;
        p = atomicAdd(&g_cnt[cc.x], 1); g_col[p] = uu.x;
        p = atomicAdd(&g_cnt[uu.y], 1); g_col[p] = cc.y;
        p = atomicAdd(&g_cnt[cc.y], 1); g_col[p] = uu.y;
        p = atomicAdd(&g_cnt[uu.z], 1); g_col[p] = cc.z;
        p = atomicAdd(&g_cnt[cc.z], 1); g_col[p] = uu.z;
        p = atomicAdd(&g_cnt[uu.w], 1); g_col[p] = cc.w;
        p = atomicAdd(&g_cnt[cc.w], 1); g_col[p] = uu.w;
    }
}

// ---------------------------------------------------------------------------
// Launches 3-5: SpMM over degree-sorted rows: t[r] = sum s[c]; s_next = t/deg.
// FOUR rows/warp, 8 lanes/row, uint4 = 8 halves/lane.
// 16-edge chunks (MLP=16 gathers in flight per row-group — the measured
// binding knob); dummy-row-NN padding is L1-resident and ~free.
// ---------------------------------------------------------------------------
template <int L>
__global__ void __launch_bounds__(256) k_spmm() {
    const uint4* __restrict__ src4 =
        (const uint4*)(L == 0 ? g_s0 : L == 1 ? g_s1 : g_s2);
    uint4* __restrict__ dst4 =
        (uint4*)(L == 0 ? g_s1 : L == 1 ? g_s2 : g_s3);

    __shared__ int smc[8][4][17];   // [warp][row-in-warp][16 + pad]
    int lane = threadIdx.x & 31;
    int w    = threadIdx.x >> 5;
    int q    = lane >> 3;
    int sub  = lane & 7;

    int ri = blockIdx.x * 32 + (w << 2) + q;    // position in sorted order
    bool valid = ri < NN;
    int r = 0, s = 0, deg = 0;
    if (valid) {
        r   = g_perm[ri];
        s   = g_rowptr[r];
        deg = g_rowptr[r + 1] - s;
    }
    int trip = deg;
    trip = max(trip, __shfl_xor_sync(0xffffffffu, trip, 8));
    trip = max(trip, __shfl_xor_sync(0xffffffffu, trip, 16));

    half2 a0 = __float2half2_rn(0.f), a1 = a0, a2 = a0, a3 = a0;

    for (int k = 0; k < trip; k += 16) {
        int i0 = k + sub, i1 = k + 8 + sub;
        smc[w][q][sub]     = (i0 < deg) ? __ldg(&g_col[s + i0]) : NN;
        smc[w][q][8 + sub] = (i1 < deg) ? __ldg(&g_col[s + i1]) : NN;
        __syncwarp();
#pragma unroll
        for (int j = 0; j < 16; ++j) {
            int cj = smc[w][q][j];          // broadcast within row-group
            uint4 v = src4[cj * 8 + sub];   // LDG.128: 8 halves (row NN = 0)
            a0 = __hadd2(a0, *(half2*)&v.x);
            a1 = __hadd2(a1, *(half2*)&v.y);
            a2 = __hadd2(a2, *(half2*)&v.z);
            a3 = __hadd2(a3, *(half2*)&v.w);
        }
        __syncwarp();
    }

    if (valid) {
        float isq2 = 1.f / fmaxf((float)deg, 1.f);   // isq^2 == 1/deg
        float2 f0 = __half22float2(a0), f1 = __half22float2(a1);
        float2 f2 = __half22float2(a2), f3 = __half22float2(a3);
        half2 h0 = __floats2half2_rn(f0.x * isq2, f0.y * isq2);
        half2 h1 = __floats2half2_rn(f1.x * isq2, f1.y * isq2);
        half2 h2 = __floats2half2_rn(f2.x * isq2, f2.y * isq2);
        half2 h3 = __floats2half2_rn(f3.x * isq2, f3.y * isq2);
        uint4 o;
        o.x = *(unsigned*)&h0; o.y = *(unsigned*)&h1;
        o.z = *(unsigned*)&h2; o.w = *(unsigned*)&h3;
        dst4[r * 8 + sub] = o;              // STG.128 (128B per row)
    }
}

// ---------------------------------------------------------------------------
// Launch 6: scorer + replay-state reset
// ---------------------------------------------------------------------------
__global__ void k_score(const int* __restrict__ uids, const int* __restrict__ iids,
                        const float2* __restrict__ ue2, const float2* __restrict__ ie2,
                        float* __restrict__ out) {
    int gtid = blockIdx.x * blockDim.x + threadIdx.x;
    int w = gtid >> 5;
    int lane = threadIdx.x & 31;
    if (w < BB) {
        const half2* s1 = (const half2*)g_s1;
        const half2* s2 = (const half2*)g_s2;
        const half2* s3 = (const half2*)g_s3;

        int u  = uids[w];
        int ri = NU + iids[w];

        int du = g_rowptr[u + 1] - g_rowptr[u];
        float sdu = sqrtf(fmaxf((float)du, 1.f));
        int ou = u * 32 + lane;
        float2 x0u = ue2[ou];
        float2 a = __half22float2(s1[ou]);
        float2 b = __half22float2(s2[ou]);
        float2 c = __half22float2(s3[ou]);
        float eux = x0u.x + sdu * (a.x + b.x + c.x);
        float euy = x0u.y + sdu * (a.y + b.y + c.y);

        int di = g_rowptr[ri + 1] - g_rowptr[ri];
        float sdi = sqrtf(fmaxf((float)di, 1.f));
        int oi = ri * 32 + lane;
        float2 x0i = ie2[oi - NU * 32];
        float2 d = __half22float2(s1[oi]);
        float2 f = __half22float2(s2[oi]);
        float2 g = __half22float2(s3[oi]);
        float eix = x0i.x + sdi * (d.x + f.x + g.x);
        float eiy = x0i.y + sdi * (d.y + f.y + g.y);

        float sres = eux * eix + euy * eiy;
#pragma unroll
        for (int o = 16; o; o >>= 1) sres += __shfl_xor_sync(0xffffffffu, sres, o);
        if (lane == 0) out[w] = sres * 0.0625f;   // 1/(L+1)^2
    }
    // reset replay state
    int stride = gridDim.x * blockDim.x;
    for (int i = gtid; i < NN; i += stride) g_cnt[i] = 0;
    for (int i = gtid; i < NB1; i += stride) g_tile_desc[i] = 0ull;
    for (int i = gtid; i < NBIN; i += stride) { g_bin[i] = 0; g_binoff[i] = 0; }
}

// ---------------------------------------------------------------------------
extern "C" void kernel_launch(void* const* d_in, const int* in_sizes, int n_in,
                              void* d_out, int out_size) {
    const float* ue   = (const float*)d_in[0];
    const float* ie   = (const float*)d_in[1];
    // d_in[2] (adj_vals) unused: vals == isq[r]*isq[c], rebuilt from degrees
    const int*   rows = (const int*)  d_in[3];
    const int*   cols = (const int*)  d_in[4];
    const int*   uids = (const int*)  d_in[5];
    const int*   iids = (const int*)  d_in[6];
    float*       out  = (float*)d_out;

    k_hist        <<< 2048, 256 >>>((const int4*)rows, (const int4*)cols);  // 0
    k_scan        <<< NB1, SCAN_BS >>>();                                   // 1
    k_prep_scatter<<< 2048, 256 >>>((const float4*)ue, (const float4*)ie,
                                    (const int4*)rows, (const int4*)cols);  // 2

    const int spmm_blocks = (NN + 31) / 32;                   // 4688
    k_spmm<0><<< spmm_blocks, 256 >>>();                      // 3 <- ncu capture
    k_spmm<1><<< spmm_blocks, 256 >>>();                      // 4
    k_spmm<2><<< spmm_blocks, 256 >>>();                      // 5

    k_score<<< 512, 256 >>>(uids, iids, (const float2*)ue, (const float2*)ie, out);  // 6
}